// round 7
// baseline (speedup 1.0000x reference)
#include <cuda_runtime.h>

#define NB      32768
#define ITEMS   64    // items per CTA
#define SLOTS   8
#define WBLK    258   // u64 per to-block: 32 kp * 8 + 2 pad

__device__ float g_score[64];
__device__ float g_Q1[64 * 64];   // embed[t] @ rh_w1[0:64] + rh_b1
__device__ float g_E1[64 * 64];   // (1/8) * embed[t] @ rh_w1[64:128]

typedef unsigned long long u64;
typedef unsigned int u32;

#define FFMA2(acc, x, y)   asm("fma.rn.f32x2 %0, %1, %2, %0;" : "+l"(acc) : "l"(x), "l"(y))
#define ADD2(acc, v)       asm("add.rn.f32x2 %0, %0, %1;"     : "+l"(acc) : "l"(v))
#define PACK2(d, lo, hi)   asm("mov.b64 %0, {%1, %2};" : "=l"(d) : "f"(lo), "f"(hi))
#define UNPACK2(lo, hi, s) asm("mov.b64 {%0, %1}, %2;" : "=f"(lo), "=f"(hi) : "l"(s))

// Dynamic smem layout (bytes)
#define OFF_E1   0                       // float[64*68]        = 17408
#define OFF_A    17408                   // ulonglong2[16*64]   = 16384  ([kk][item], XOR swizzled)
#define OFF_W    33792                   // u64[8*258]          = 16512
#define OFF_SC   50304                   // float[64]
#define OFF_B2   50560                   // float[64]
#define OFF_TOK  50816                   // u64[64]
#define OFF_Q    51328                   // int[64]
#define SMEM_TOTAL 51584

// ---------------------------------------------------------------------------
__global__ void __launch_bounds__(128) precompute_k(
    const float* __restrict__ emb,
    const float* __restrict__ sw1, const float* __restrict__ sb1,
    const float* __restrict__ sw2, const float* __restrict__ sb2,
    const float* __restrict__ w1,  const float* __restrict__ b1)
{
    const int t   = blockIdx.x;
    const int tid = threadIdx.x;
    __shared__ float s_e[64];
    if (tid < 16) ((float4*)s_e)[tid] = ((const float4*)(emb + t * 64))[tid];
    __syncthreads();

    const int half = tid >> 6;
    const int o    = tid & 63;
    const float* wcol = w1 + half * 64 * 64 + o;
    float acc = half ? 0.0f : b1[o];
#pragma unroll
    for (int k = 0; k < 64; k++) acc = fmaf(s_e[k], wcol[k * 64], acc);
    if (half) g_E1[t * 64 + o] = acc * 0.125f;
    else      g_Q1[t * 64 + o] = acc;

    if (tid < 32) {
        float h = sb1[tid];
#pragma unroll
        for (int d = 0; d < 64; d++) h = fmaf(s_e[d], sw1[d * 32 + tid], h);
        float p = fmaxf(h, 0.0f) * sw2[tid];
#pragma unroll
        for (int off = 16; off > 0; off >>= 1)
            p += __shfl_down_sync(0xffffffffu, p, off);
        if (tid == 0) g_score[t] = p + sb2[0];
    }
}

// ---------------------------------------------------------------------------
// main_k: 512 CTAs x 256 threads, 64 items/CTA (3 CTAs/SM -> ~24 warps/SM).
//  1a: threads 0-63 scan WHILE threads 64-255 stage E1/W2
//  1b: all 8 warps: conflict-free gather -> swizzled A[kk][item]
//  2 : register-tiled GEMM: 2 items x 8 outs per thread, f32x2 FMA
// ---------------------------------------------------------------------------
__global__ void __launch_bounds__(256, 3) main_k(
    const int*   __restrict__ seqs,
    const int*   __restrict__ qtok,
    const float* __restrict__ w2,    // (64 k, 64 o)
    const float* __restrict__ b2,
    float*       __restrict__ out)
{
    extern __shared__ __align__(16) char dyn[];
    float*      s_E1  = (float*)(dyn + OFF_E1);
    ulonglong2* s_A2  = (ulonglong2*)(dyn + OFF_A);
    u64*        s_W   = (u64*)(dyn + OFF_W);
    float*      s_sc  = (float*)(dyn + OFF_SC);
    float*      s_b2  = (float*)(dyn + OFF_B2);
    u64*        s_tok = (u64*)(dyn + OFF_TOK);
    int*        s_q   = (int*)(dyn + OFF_Q);

    const int tid = threadIdx.x;

    // score table + bias first (scan needs s_sc)
    if (tid < 64) { s_sc[tid] = g_score[tid]; s_b2[tid] = b2[tid]; }
    __syncthreads();

    if (tid < ITEMS) {
        // =============== threads 0-63: eviction scan (byte-packed tokens) ===============
        const int item = blockIdx.x * ITEMS + tid;
        const int4* sp = (const int4*)seqs + item * 8;
        u32 w8[8];
#pragma unroll
        for (int g = 0; g < 8; g++) {
            const int4 v = sp[g];
            w8[g] = (u32)(v.x & 63) | ((u32)(v.y & 63) << 8) |
                    ((u32)(v.z & 63) << 16) | ((u32)(v.w & 63) << 24);
        }
        int   tok[SLOTS];
        float sc [SLOTS];
#pragma unroll
        for (int j = 0; j < SLOTS; j++) {
            tok[j] = (int)((w8[j >> 2] >> ((j & 3) * 8)) & 63u);
            sc[j]  = s_sc[tok[j]];
        }
#pragma unroll
        for (int step = 8; step < 31; step++) {
            const int   nt = (int)((w8[step >> 2] >> ((step & 3) * 8)) & 63u);
            const float ns = s_sc[nt];
            float best = sc[0]; int bi = 0;
#pragma unroll
            for (int j = 1; j < SLOTS; j++)
                if (sc[j] < best) { best = sc[j]; bi = j; }
#pragma unroll
            for (int j = 0; j < SLOTS - 1; j++)
                if (j >= bi) { tok[j] = tok[j + 1]; sc[j] = sc[j + 1]; }
            tok[SLOTS - 1] = nt; sc[SLOTS - 1] = ns;
        }
        u64 t8 = 0;
#pragma unroll
        for (int s = 0; s < SLOTS; s++) t8 |= (u64)(u32)tok[s] << (8 * s);
        s_tok[tid] = t8;
        s_q[tid]   = qtok[item] & 63;
    } else {
        // =============== threads 64-255: stage E1 + W2 (overlapped with scan) ===============
        const int t2 = tid - 64;          // 0..191
        for (int i4 = t2; i4 < 1024; i4 += 192) {
            const float4 e = ((const float4*)g_E1)[i4];
            *(float4*)(s_E1 + (i4 >> 4) * 68 + (i4 & 15) * 4) = e;
        }
        for (int e = t2; e < 2048; e += 192) {
            const int to = e >> 8, rem = e & 255, kp = rem >> 3, j = rem & 7;
            const int o  = to * 8 + j;
            u64 v;
            PACK2(v, w2[kp * 128 + o], w2[kp * 128 + 64 + o]);
            s_W[to * WBLK + kp * 8 + j] = v;
        }
    }
    __syncthreads();

    // =============== phase 1b: cooperative gather (8 warps, 2 items/warp/pass) ===============
    {
        const int lane = tid & 31;
        const int wrp  = tid >> 5;
        const int o4   = lane & 15;       // float4 index within row == kk
        const int hi16 = lane >> 4;
        const ulonglong2* E1q = (const ulonglong2*)s_E1;
        const ulonglong2* Q1q = (const ulonglong2*)g_Q1;
#pragma unroll
        for (int p = 0; p < 4; p++) {
            const int it = wrp * 8 + 2 * p + hi16;
            const u64 t8 = s_tok[it];
            const int q  = s_q[it];
            const ulonglong2 qv = Q1q[q * 16 + o4];   // L1-hot LDG.128
            u64 P0 = qv.x, P1 = qv.y;
#pragma unroll
            for (int s = 0; s < SLOTS; s++) {
                const int tk = (int)((t8 >> (8 * s)) & 63);
                const ulonglong2 ev = E1q[tk * 17 + o4];
                ADD2(P0, ev.x);
                ADD2(P1, ev.y);
            }
            float f0, f1, f2, f3;
            UNPACK2(f0, f1, P0); UNPACK2(f2, f3, P1);
            f0 = fmaxf(f0, 0.0f); f1 = fmaxf(f1, 0.0f);
            f2 = fmaxf(f2, 0.0f); f3 = fmaxf(f3, 0.0f);
            ulonglong2 st;
            PACK2(st.x, f0, f1); PACK2(st.y, f2, f3);
            s_A2[o4 * 64 + (it ^ (o4 & 7))] = st;     // swizzled
        }
    }
    __syncthreads();

    // =============== phase 2: register-tiled GEMM (2 items x 8 outs) ===============
    const int to = tid & 7;               // output group
    const int ti = tid >> 3;              // item lane 0..31; items {ti, ti+32}
    float bb[8];
#pragma unroll
    for (int j = 0; j < 8; j++) bb[j] = s_b2[to * 8 + j];

    const u64* wblk = s_W + to * WBLK;

    u64 acc[16];
#pragma unroll
    for (int i = 0; i < 16; i++) acc[i] = 0ull;

#pragma unroll 4
    for (int kk = 0; kk < 16; kk++) {
        const int z = kk & 7;
        const ulonglong2 av0 = s_A2[kk * 64 + (ti ^ z)];          // 4-addr broadcast
        const ulonglong2 av1 = s_A2[kk * 64 + ((ti + 32) ^ z)];
        u64 W0[8], W1[8];
        const ulonglong2* wp0 = (const ulonglong2*)(wblk + (2 * kk) * 8);
        const ulonglong2* wp1 = (const ulonglong2*)(wblk + (2 * kk + 1) * 8);
#pragma unroll
        for (int c = 0; c < 4; c++) {
            const ulonglong2 a = wp0[c]; W0[2 * c] = a.x; W0[2 * c + 1] = a.y;
            const ulonglong2 b = wp1[c]; W1[2 * c] = b.x; W1[2 * c + 1] = b.y;
        }
#pragma unroll
        for (int j = 0; j < 8; j++) {
            FFMA2(acc[j],     av0.x, W0[j]);
            FFMA2(acc[j],     av0.y, W1[j]);
            FFMA2(acc[8 + j], av1.x, W0[j]);
            FFMA2(acc[8 + j], av1.y, W1[j]);
        }
    }

    // epilogue: coalesced STG
#pragma unroll
    for (int i2 = 0; i2 < 2; i2++) {
        float r[8];
#pragma unroll
        for (int j = 0; j < 8; j++) {
            float lo, hi;
            UNPACK2(lo, hi, acc[8 * i2 + j]);
            r[j] = lo + hi + bb[j];
        }
        const int item = blockIdx.x * ITEMS + ti + 32 * i2;
        float* orow = out + (size_t)item * 64 + to * 8;
        *(float4*)(orow)     = make_float4(r[0], r[1], r[2], r[3]);
        *(float4*)(orow + 4) = make_float4(r[4], r[5], r[6], r[7]);
    }
}

// ---------------------------------------------------------------------------
extern "C" void kernel_launch(void* const* d_in, const int* in_sizes, int n_in,
                              void* d_out, int out_size)
{
    const int*   seqs = (const int*)  d_in[0];
    const int*   qtok = (const int*)  d_in[1];
    const float* emb  = (const float*)d_in[2];
    const float* sw1  = (const float*)d_in[3];
    const float* sb1  = (const float*)d_in[4];
    const float* sw2  = (const float*)d_in[5];
    const float* sb2  = (const float*)d_in[6];
    const float* w1   = (const float*)d_in[7];
    const float* b1   = (const float*)d_in[8];
    const float* w2   = (const float*)d_in[9];
    const float* b2   = (const float*)d_in[10];
    float* out = (float*)d_out;

    cudaFuncSetAttribute(main_k, cudaFuncAttributeMaxDynamicSharedMemorySize, SMEM_TOTAL);

    precompute_k<<<64, 128>>>(emb, sw1, sb1, sw2, sb2, w1, b1);
    main_k<<<NB / ITEMS, 256, SMEM_TOTAL>>>(seqs, qtok, w2, b2, out);
}

// round 8
// speedup vs baseline: 1.2947x; 1.2947x over previous
#include <cuda_runtime.h>

#define NB      32768
#define SLOTS   8
#define WBLK    258   // u64 per to-block: 32 kp * 8 + 2 pad

__device__ float g_score[64];
__device__ float g_Q1[64 * 64];   // embed[t] @ rh_w1[0:64] + rh_b1
__device__ float g_E1[64 * 64];   // (1/8) * embed[t] @ rh_w1[64:128]

typedef unsigned long long u64;
typedef unsigned int u32;

#define FFMA2(acc, x, y)   asm("fma.rn.f32x2 %0, %1, %2, %0;" : "+l"(acc) : "l"(x), "l"(y))
#define ADD2T(d, x, y)     asm("add.rn.f32x2 %0, %1, %2;"     : "=l"(d)  : "l"(x), "l"(y))
#define PACK2(d, lo, hi)   asm("mov.b64 %0, {%1, %2};" : "=l"(d) : "f"(lo), "f"(hi))
#define UNPACK2(lo, hi, s) asm("mov.b64 {%0, %1}, %2;" : "=f"(lo), "=f"(hi) : "l"(s))

// Dynamic smem layout (bytes)
#define OFF_E1   0                       // float[64*68]   = 17408
#define OFF_A    17408                   // ulonglong2[16*128] = 32768 ([kk][item], XOR swizzled)
#define OFF_W    50176                   // u64[8*258]     = 16512
#define OFF_SC   66688                   // float[64]
#define OFF_B2   66944                   // float[64]
#define OFF_TOK  67200                   // u64[128]
#define OFF_Q    68224                   // int[128]
#define OFF_RK   68736                   // u32[64]
#define SMEM_TOTAL 68992

// ---------------------------------------------------------------------------
__global__ void __launch_bounds__(128) precompute_k(
    const float* __restrict__ emb,
    const float* __restrict__ sw1, const float* __restrict__ sb1,
    const float* __restrict__ sw2, const float* __restrict__ sb2,
    const float* __restrict__ w1,  const float* __restrict__ b1)
{
    const int t   = blockIdx.x;
    const int tid = threadIdx.x;
    __shared__ float s_e[64];
    if (tid < 16) ((float4*)s_e)[tid] = ((const float4*)(emb + t * 64))[tid];
    __syncthreads();

    const int half = tid >> 6;
    const int o    = tid & 63;
    const float* wcol = w1 + half * 64 * 64 + o;
    float acc = half ? 0.0f : b1[o];
#pragma unroll
    for (int k = 0; k < 64; k++) acc = fmaf(s_e[k], wcol[k * 64], acc);
    if (half) g_E1[t * 64 + o] = acc * 0.125f;
    else      g_Q1[t * 64 + o] = acc;

    if (tid < 32) {
        float h = sb1[tid];
#pragma unroll
        for (int d = 0; d < 64; d++) h = fmaf(s_e[d], sw1[d * 32 + tid], h);
        float p = fmaxf(h, 0.0f) * sw2[tid];
#pragma unroll
        for (int off = 16; off > 0; off >>= 1)
            p += __shfl_down_sync(0xffffffffu, p, off);
        if (tid == 0) g_score[t] = p + sb2[0];
    }
}

// ---------------------------------------------------------------------------
// main_k: 256 CTAs x 256 threads, 128 items/CTA (2 CTAs/SM, single wave).
//  rank:  threads 64-127 build integer rank-keys from score table
//  1a:    threads 0-127 scan in key space WHILE threads 128-255 stage E1/W2
//  1b:    all warps: conflict-free gather with tree-adds -> swizzled A
//  2 :    register-tiled GEMM: 4 items x 8 outs, f32x2 FMA
// ---------------------------------------------------------------------------
__global__ void __launch_bounds__(256, 2) main_k(
    const int*   __restrict__ seqs,
    const int*   __restrict__ qtok,
    const float* __restrict__ w2,    // (64 k, 64 o)
    const float* __restrict__ b2,
    float*       __restrict__ out)
{
    extern __shared__ __align__(16) char dyn[];
    float*      s_E1  = (float*)(dyn + OFF_E1);
    ulonglong2* s_A2  = (ulonglong2*)(dyn + OFF_A);
    u64*        s_W   = (u64*)(dyn + OFF_W);
    float*      s_sc  = (float*)(dyn + OFF_SC);
    float*      s_b2  = (float*)(dyn + OFF_B2);
    u64*        s_tok = (u64*)(dyn + OFF_TOK);
    int*        s_q   = (int*)(dyn + OFF_Q);
    u32*        s_rk  = (u32*)(dyn + OFF_RK);

    const int tid = threadIdx.x;

    if (tid < 64) { s_sc[tid] = g_score[tid]; s_b2[tid] = b2[tid]; }
    __syncthreads();

    // rank keys: rank = #{u : score[u] < score[t]}  (equal scores -> equal rank,
    // so (rank, insertion_ctr) ordering == reference first-minimum tie-break)
    if (tid >= 64 && tid < 128) {
        const int t = tid - 64;
        const float st = s_sc[t];
        int r = 0;
#pragma unroll 16
        for (int u = 0; u < 64; u++) r += (s_sc[u] < st);
        s_rk[t] = ((u32)r << 11) | (u32)t;
    }
    __syncthreads();

    if (tid < 128) {
        // =============== threads 0-127: eviction scan (integer keys) ===============
        const int item = blockIdx.x * 128 + tid;
        const int4* sp = (const int4*)seqs + item * 8;
        u32 w8[8];
#pragma unroll
        for (int g = 0; g < 8; g++) {
            const int4 v = sp[g];
            w8[g] = (u32)(v.x & 63) | ((u32)(v.y & 63) << 8) |
                    ((u32)(v.z & 63) << 16) | ((u32)(v.w & 63) << 24);
        }
        // preload all 31 keys: rank<<11 | step<<6 | token   (batched LDS)
        u32 k31[31];
#pragma unroll
        for (int j = 0; j < 31; j++) {
            const u32 t = (w8[j >> 2] >> ((j & 3) * 8)) & 63u;
            k31[j] = s_rk[t] + ((u32)j << 6);
        }
        u32 key[SLOTS];
#pragma unroll
        for (int j = 0; j < SLOTS; j++) key[j] = k31[j];

#pragma unroll
        for (int step = 8; step < 31; step++) {
            // min-tree (unique minimum: counters distinct)
            const u32 m01 = umin(key[0], key[1]);
            const u32 m23 = umin(key[2], key[3]);
            const u32 m45 = umin(key[4], key[5]);
            const u32 m67 = umin(key[6], key[7]);
            const u32 m03 = umin(m01, m23);
            const u32 m47 = umin(m45, m67);
            const u32 mk  = umin(m03, m47);
            const u32 nk  = k31[step];
#pragma unroll
            for (int j = 0; j < SLOTS; j++)
                key[j] = (key[j] == mk) ? nk : key[j];
        }
        u64 t8 = 0;
#pragma unroll
        for (int s = 0; s < SLOTS; s++) t8 |= (u64)(key[s] & 63u) << (8 * s);
        s_tok[tid] = t8;
        s_q[tid]   = qtok[item] & 63;
    } else {
        // =============== threads 128-255: stage E1 + W2 (overlapped) ===============
        const int t2 = tid - 128;
#pragma unroll
        for (int i4 = t2; i4 < 1024; i4 += 128) {
            const float4 e = ((const float4*)g_E1)[i4];
            *(float4*)(s_E1 + (i4 >> 4) * 68 + (i4 & 15) * 4) = e;
        }
#pragma unroll
        for (int e = t2; e < 2048; e += 128) {
            const int to = e >> 8, rem = e & 255, kp = rem >> 3, j = rem & 7;
            const int o  = to * 8 + j;
            u64 v;
            PACK2(v, w2[kp * 128 + o], w2[kp * 128 + 64 + o]);
            s_W[to * WBLK + kp * 8 + j] = v;
        }
    }
    __syncthreads();

    // =============== phase 1b: cooperative gather (tree adds) ===============
    {
        const int lane = tid & 31;
        const int wrp  = tid >> 5;
        const int o4   = lane & 15;
        const int hi16 = lane >> 4;
        const ulonglong2* E1q = (const ulonglong2*)s_E1;
        const ulonglong2* Q1q = (const ulonglong2*)g_Q1;
#pragma unroll
        for (int p = 0; p < 8; p++) {
            const int it = wrp * 16 + 2 * p + hi16;
            const u64 t8 = s_tok[it];
            const int q  = s_q[it];
            const ulonglong2 qv = Q1q[q * 16 + o4];
            // batch all 8 loads (independent), then 4-deep tree
            ulonglong2 ev[SLOTS];
#pragma unroll
            for (int s = 0; s < SLOTS; s++)
                ev[s] = E1q[((int)((t8 >> (8 * s)) & 63)) * 17 + o4];
            u64 x0, x1, x2, x3, y0, y1, z0;
            ADD2T(x0, ev[0].x, ev[1].x); ADD2T(x1, ev[2].x, ev[3].x);
            ADD2T(x2, ev[4].x, ev[5].x); ADD2T(x3, ev[6].x, ev[7].x);
            ADD2T(y0, x0, x1); ADD2T(y1, x2, x3);
            ADD2T(z0, y0, y1);
            u64 P0; ADD2T(P0, z0, qv.x);
            ADD2T(x0, ev[0].y, ev[1].y); ADD2T(x1, ev[2].y, ev[3].y);
            ADD2T(x2, ev[4].y, ev[5].y); ADD2T(x3, ev[6].y, ev[7].y);
            ADD2T(y0, x0, x1); ADD2T(y1, x2, x3);
            ADD2T(z0, y0, y1);
            u64 P1; ADD2T(P1, z0, qv.y);

            float f0, f1, f2, f3;
            UNPACK2(f0, f1, P0); UNPACK2(f2, f3, P1);
            f0 = fmaxf(f0, 0.0f); f1 = fmaxf(f1, 0.0f);
            f2 = fmaxf(f2, 0.0f); f3 = fmaxf(f3, 0.0f);
            ulonglong2 st;
            PACK2(st.x, f0, f1); PACK2(st.y, f2, f3);
            s_A2[o4 * 128 + (it ^ (o4 & 7))] = st;
        }
    }
    __syncthreads();

    // =============== phase 2: register-tiled GEMM (4 items x 8 outs) ===============
    const int to = tid & 7;
    const int ti = tid >> 3;
    float bb[8];
#pragma unroll
    for (int j = 0; j < 8; j++) bb[j] = s_b2[to * 8 + j];

    const u64* wblk = s_W + to * WBLK;

    u64 acc[32];
#pragma unroll
    for (int i = 0; i < 32; i++) acc[i] = 0ull;

#pragma unroll 4
    for (int kk = 0; kk < 16; kk++) {
        const int z = kk & 7;
        u64 A0[4], A1[4];
#pragma unroll
        for (int i2 = 0; i2 < 4; i2++) {
            const ulonglong2 av = s_A2[kk * 128 + ((ti + 32 * i2) ^ z)];
            A0[i2] = av.x; A1[i2] = av.y;
        }
        u64 W0[8], W1[8];
        const ulonglong2* wp0 = (const ulonglong2*)(wblk + (2 * kk) * 8);
        const ulonglong2* wp1 = (const ulonglong2*)(wblk + (2 * kk + 1) * 8);
#pragma unroll
        for (int c = 0; c < 4; c++) {
            const ulonglong2 a = wp0[c]; W0[2 * c] = a.x; W0[2 * c + 1] = a.y;
            const ulonglong2 b = wp1[c]; W1[2 * c] = b.x; W1[2 * c + 1] = b.y;
        }
#pragma unroll
        for (int i2 = 0; i2 < 4; i2++)
#pragma unroll
            for (int j = 0; j < 8; j++) {
                FFMA2(acc[i2 * 8 + j], A0[i2], W0[j]);
                FFMA2(acc[i2 * 8 + j], A1[i2], W1[j]);
            }
    }

    // epilogue: coalesced STG
#pragma unroll
    for (int i2 = 0; i2 < 4; i2++) {
        float r[8];
#pragma unroll
        for (int j = 0; j < 8; j++) {
            float lo, hi;
            UNPACK2(lo, hi, acc[i2 * 8 + j]);
            r[j] = lo + hi + bb[j];
        }
        const int item = blockIdx.x * 128 + ti + 32 * i2;
        float* orow = out + (size_t)item * 64 + to * 8;
        *(float4*)(orow)     = make_float4(r[0], r[1], r[2], r[3]);
        *(float4*)(orow + 4) = make_float4(r[4], r[5], r[6], r[7]);
    }
}

// ---------------------------------------------------------------------------
extern "C" void kernel_launch(void* const* d_in, const int* in_sizes, int n_in,
                              void* d_out, int out_size)
{
    const int*   seqs = (const int*)  d_in[0];
    const int*   qtok = (const int*)  d_in[1];
    const float* emb  = (const float*)d_in[2];
    const float* sw1  = (const float*)d_in[3];
    const float* sb1  = (const float*)d_in[4];
    const float* sw2  = (const float*)d_in[5];
    const float* sb2  = (const float*)d_in[6];
    const float* w1   = (const float*)d_in[7];
    const float* b1   = (const float*)d_in[8];
    const float* w2   = (const float*)d_in[9];
    const float* b2   = (const float*)d_in[10];
    float* out = (float*)d_out;

    cudaFuncSetAttribute(main_k, cudaFuncAttributeMaxDynamicSharedMemorySize, SMEM_TOTAL);

    precompute_k<<<64, 128>>>(emb, sw1, sb1, sw2, sb2, w1, b1);
    main_k<<<NB / 128, 256, SMEM_TOTAL>>>(seqs, qtok, w2, b2, out);
}

// round 11
// speedup vs baseline: 1.6091x; 1.2429x over previous
#include <cuda_runtime.h>

#define NB      32768
#define SLOTS   8

__device__ float g_score[64];
__device__ float g_Q1[64 * 64];   // embed[t] @ rh_w1[0:64] + rh_b1
__device__ float g_E1[64 * 64];   // (1/8) * embed[t] @ rh_w1[64:128]

typedef unsigned long long u64;
typedef unsigned int u32;

__device__ u64 g_Bh[1024];        // W2 hi-bf16 mma B-fragments [tile=kt*8+nt][lane]
__device__ u64 g_Bl[1024];        // W2 lo-bf16 fragments

#define ADD2T(d, x, y)     asm("add.rn.f32x2 %0, %1, %2;" : "=l"(d) : "l"(x), "l"(y))
#define PACK2(d, lo, hi)   asm("mov.b64 %0, {%1, %2};" : "=l"(d) : "f"(lo), "f"(hi))
#define UNPACK2(lo, hi, s) asm("mov.b64 {%0, %1}, %2;" : "=f"(lo), "=f"(hi) : "l"(s))
// pack two f32 -> bf16x2 (first operand -> high half)
#define CVTP(d, fhi, flo)  asm("cvt.rn.bf16x2.f32 %0, %1, %2;" : "=r"(d) : "f"(fhi), "f"(flo))
#define MMA4(d0,d1,d2,d3,a0,a1,a2,a3,b0,b1) \
    asm("mma.sync.aligned.m16n8k16.row.col.f32.bf16.bf16.f32 " \
        "{%0,%1,%2,%3},{%4,%5,%6,%7},{%8,%9},{%0,%1,%2,%3};" \
        : "+f"(d0),"+f"(d1),"+f"(d2),"+f"(d3) \
        : "r"(a0),"r"(a1),"r"(a2),"r"(a3),"r"(b0),"r"(b1))

// Dynamic smem layout (bytes)
#define OFF_E1   0          // float[64*68]  = 17408
#define OFF_AHI  17408      // u32[128*36]   = 18432  (A hi bf16x2, stride 36)
#define OFF_ALO  35840      // u32[128*36]   = 18432
#define OFF_BH   54272      // u64[1024]     = 8192
#define OFF_BL   62464      // u64[1024]     = 8192
#define OFF_SC   70656      // float[64]
#define OFF_B2   70912      // float[64]
#define OFF_TOK  71168      // u64[128]
#define OFF_Q    72192      // int[128]
#define OFF_RK   72704      // u32[64]
#define SMEM_TOTAL 72960

// ---------------------------------------------------------------------------
// precompute: blocks 0-63 = tables; blocks 64-71 = W2 B-fragments
// ---------------------------------------------------------------------------
__global__ void __launch_bounds__(128) precompute_k(
    const float* __restrict__ emb,
    const float* __restrict__ sw1, const float* __restrict__ sb1,
    const float* __restrict__ sw2, const float* __restrict__ sb2,
    const float* __restrict__ w1,  const float* __restrict__ b1,
    const float* __restrict__ w2)
{
    const int tid = threadIdx.x;
    if (blockIdx.x >= 64) {
        const int e  = (blockIdx.x - 64) * 128 + tid;
        if (e < 1024) {
            const int tile = e >> 5, l = e & 31;
            const int kt = tile >> 3, nt = tile & 7;
            const int k0 = kt * 16 + (l & 3) * 2;
            const int n  = nt * 8 + (l >> 2);
            const float f00 = w2[k0 * 64 + n],       f01 = w2[(k0 + 1) * 64 + n];
            const float f10 = w2[(k0 + 8) * 64 + n], f11 = w2[(k0 + 9) * 64 + n];
            u32 b0h, b1h, b0l, b1l;
            CVTP(b0h, f01, f00);
            CVTP(b1h, f11, f10);
            const float h00 = __uint_as_float(b0h << 16), h01 = __uint_as_float(b0h & 0xFFFF0000u);
            const float h10 = __uint_as_float(b1h << 16), h11 = __uint_as_float(b1h & 0xFFFF0000u);
            CVTP(b0l, f01 - h01, f00 - h00);
            CVTP(b1l, f11 - h11, f10 - h10);
            g_Bh[e] = (u64)b0h | ((u64)b1h << 32);
            g_Bl[e] = (u64)b0l | ((u64)b1l << 32);
        }
        return;
    }

    const int t = blockIdx.x;
    __shared__ float s_e[64];
    if (tid < 16) ((float4*)s_e)[tid] = ((const float4*)(emb + t * 64))[tid];
    __syncthreads();

    const int half = tid >> 6;
    const int o    = tid & 63;
    const float* wcol = w1 + half * 64 * 64 + o;
    float acc = half ? 0.0f : b1[o];
#pragma unroll
    for (int k = 0; k < 64; k++) acc = fmaf(s_e[k], wcol[k * 64], acc);
    if (half) g_E1[t * 64 + o] = acc * 0.125f;
    else      g_Q1[t * 64 + o] = acc;

    if (tid < 32) {
        float h = sb1[tid];
#pragma unroll
        for (int d = 0; d < 64; d++) h = fmaf(s_e[d], sw1[d * 32 + tid], h);
        float p = fmaxf(h, 0.0f) * sw2[tid];
#pragma unroll
        for (int off = 16; off > 0; off >>= 1)
            p += __shfl_down_sync(0xffffffffu, p, off);
        if (tid == 0) g_score[t] = p + sb2[0];
    }
}

// ---------------------------------------------------------------------------
// main_k: 256 CTAs x 256 threads (8 warps), 128 items/CTA.
// ---------------------------------------------------------------------------
__global__ void __launch_bounds__(256, 2) main_k(
    const int*   __restrict__ seqs,
    const int*   __restrict__ qtok,
    const float* __restrict__ b2,
    float*       __restrict__ out)
{
    extern __shared__ __align__(16) char dyn[];
    float* s_E1  = (float*)(dyn + OFF_E1);
    u64*   s_Ahi = (u64*)(dyn + OFF_AHI);
    u64*   s_Alo = (u64*)(dyn + OFF_ALO);
    u64*   s_Bh  = (u64*)(dyn + OFF_BH);
    u64*   s_Bl  = (u64*)(dyn + OFF_BL);
    float* s_sc  = (float*)(dyn + OFF_SC);
    float* s_b2  = (float*)(dyn + OFF_B2);
    u64*   s_tok = (u64*)(dyn + OFF_TOK);
    int*   s_q   = (int*)(dyn + OFF_Q);
    u32*   s_rk  = (u32*)(dyn + OFF_RK);

    const int tid = threadIdx.x;

    if (tid < 64) { s_sc[tid] = g_score[tid]; s_b2[tid] = b2[tid]; }
    __syncthreads();

    if (tid >= 64 && tid < 128) {
        const int t = tid - 64;
        const float st = s_sc[t];
        int r = 0;
#pragma unroll 16
        for (int u = 0; u < 64; u++) r += (s_sc[u] < st);
        s_rk[t] = ((u32)r << 11) | (u32)t;
    }
    __syncthreads();

    if (tid < 128) {
        // ---- eviction scan (integer keys) ----
        const int item = blockIdx.x * 128 + tid;
        const int4* sp = (const int4*)seqs + item * 8;
        u32 w8[8];
#pragma unroll
        for (int g = 0; g < 8; g++) {
            const int4 v = sp[g];
            w8[g] = (u32)(v.x & 63) | ((u32)(v.y & 63) << 8) |
                    ((u32)(v.z & 63) << 16) | ((u32)(v.w & 63) << 24);
        }
        u32 k31[31];
#pragma unroll
        for (int j = 0; j < 31; j++) {
            const u32 t = (w8[j >> 2] >> ((j & 3) * 8)) & 63u;
            k31[j] = s_rk[t] + ((u32)j << 6);
        }
        u32 key[SLOTS];
#pragma unroll
        for (int j = 0; j < SLOTS; j++) key[j] = k31[j];
#pragma unroll
        for (int step = 8; step < 31; step++) {
            const u32 m01 = umin(key[0], key[1]);
            const u32 m23 = umin(key[2], key[3]);
            const u32 m45 = umin(key[4], key[5]);
            const u32 m67 = umin(key[6], key[7]);
            const u32 mk  = umin(umin(m01, m23), umin(m45, m67));
            const u32 nk  = k31[step];
#pragma unroll
            for (int j = 0; j < SLOTS; j++)
                key[j] = (key[j] == mk) ? nk : key[j];
        }
        u64 t8 = 0;
#pragma unroll
        for (int s = 0; s < SLOTS; s++) t8 |= (u64)(key[s] & 63u) << (8 * s);
        s_tok[tid] = t8;
        s_q[tid]   = qtok[item] & 63;
    } else {
        // ---- staging: E1 table + B fragments (overlapped with scan) ----
        const int t2 = tid - 128;
#pragma unroll
        for (int i4 = t2; i4 < 1024; i4 += 128) {
            const float4 e = ((const float4*)g_E1)[i4];
            *(float4*)(s_E1 + (i4 >> 4) * 68 + (i4 & 15) * 4) = e;
        }
#pragma unroll
        for (int i = t2; i < 512; i += 128) {
            ((ulonglong2*)s_Bh)[i] = ((const ulonglong2*)g_Bh)[i];
            ((ulonglong2*)s_Bl)[i] = ((const ulonglong2*)g_Bl)[i];
        }
    }
    __syncthreads();

    // ---- gather: layer1 tree-adds -> bf16 hi/lo A fragments (all 128 items) ----
    {
        const int lane = tid & 31;
        const int wrp  = tid >> 5;
        const int o4   = lane & 15;
        const int hi16 = lane >> 4;
        const ulonglong2* E1q = (const ulonglong2*)s_E1;
        const ulonglong2* Q1q = (const ulonglong2*)g_Q1;
#pragma unroll
        for (int p = 0; p < 8; p++) {
            const int it = wrp * 16 + 2 * p + hi16;
            const u64 t8 = s_tok[it];
            const int q  = s_q[it];
            const ulonglong2 qv = Q1q[q * 16 + o4];
            ulonglong2 ev[SLOTS];
#pragma unroll
            for (int s = 0; s < SLOTS; s++)
                ev[s] = E1q[((int)((t8 >> (8 * s)) & 63)) * 17 + o4];
            u64 x0, x1, x2, x3, y0, y1, z0, P0, P1;
            ADD2T(x0, ev[0].x, ev[1].x); ADD2T(x1, ev[2].x, ev[3].x);
            ADD2T(x2, ev[4].x, ev[5].x); ADD2T(x3, ev[6].x, ev[7].x);
            ADD2T(y0, x0, x1); ADD2T(y1, x2, x3);
            ADD2T(z0, y0, y1); ADD2T(P0, z0, qv.x);
            ADD2T(x0, ev[0].y, ev[1].y); ADD2T(x1, ev[2].y, ev[3].y);
            ADD2T(x2, ev[4].y, ev[5].y); ADD2T(x3, ev[6].y, ev[7].y);
            ADD2T(y0, x0, x1); ADD2T(y1, x2, x3);
            ADD2T(z0, y0, y1); ADD2T(P1, z0, qv.y);

            float f0, f1, f2, f3;
            UNPACK2(f0, f1, P0); UNPACK2(f2, f3, P1);
            f0 = fmaxf(f0, 0.0f); f1 = fmaxf(f1, 0.0f);
            f2 = fmaxf(f2, 0.0f); f3 = fmaxf(f3, 0.0f);
            u32 h0, h1, l0, l1;
            CVTP(h0, f1, f0);
            CVTP(h1, f3, f2);
            const float hf0 = __uint_as_float(h0 << 16), hf1 = __uint_as_float(h0 & 0xFFFF0000u);
            const float hf2 = __uint_as_float(h1 << 16), hf3 = __uint_as_float(h1 & 0xFFFF0000u);
            CVTP(l0, f1 - hf1, f0 - hf0);
            CVTP(l1, f3 - hf3, f2 - hf2);
            s_Ahi[it * 18 + o4] = (u64)h0 | ((u64)h1 << 32);
            s_Alo[it * 18 + o4] = (u64)l0 | ((u64)l1 << 32);
        }
    }
    __syncthreads();

    // ---- layer2: mma.sync bf16 3-term GEMM ----
    // 8 warps: warp w = m-block (16 items); each warp does ALL 8 n-tiles.
    {
        const int lane = tid & 31;
        const int mb   = tid >> 5;       // 0..7
        const int r0   = mb * 16 + (lane >> 2);
        const u32* Ah = (const u32*)s_Ahi;
        const u32* Al = (const u32*)s_Alo;

        u32 ah[16], al[16];
#pragma unroll
        for (int kt = 0; kt < 4; kt++) {
            const int kp = kt * 8 + (lane & 3);
            ah[4 * kt + 0] = Ah[r0 * 36 + kp];
            ah[4 * kt + 1] = Ah[(r0 + 8) * 36 + kp];
            ah[4 * kt + 2] = Ah[r0 * 36 + kp + 4];
            ah[4 * kt + 3] = Ah[(r0 + 8) * 36 + kp + 4];
            al[4 * kt + 0] = Al[r0 * 36 + kp];
            al[4 * kt + 1] = Al[(r0 + 8) * 36 + kp];
            al[4 * kt + 2] = Al[r0 * 36 + kp + 4];
            al[4 * kt + 3] = Al[(r0 + 8) * 36 + kp + 4];
        }

        const int item0 = blockIdx.x * 128 + r0;
#pragma unroll
        for (int nt = 0; nt < 8; nt++) {             // FIX: all 8 n-tiles per warp
            float d0 = 0.f, d1 = 0.f, d2 = 0.f, d3 = 0.f;
#pragma unroll
            for (int kt = 0; kt < 4; kt++) {
                const u64 bh = s_Bh[(kt * 8 + nt) * 32 + lane];
                const u64 bl = s_Bl[(kt * 8 + nt) * 32 + lane];
                const u32 bh0 = (u32)bh, bh1 = (u32)(bh >> 32);
                const u32 bl0 = (u32)bl, bl1 = (u32)(bl >> 32);
                MMA4(d0,d1,d2,d3, ah[4*kt],ah[4*kt+1],ah[4*kt+2],ah[4*kt+3], bh0,bh1);
                MMA4(d0,d1,d2,d3, ah[4*kt],ah[4*kt+1],ah[4*kt+2],ah[4*kt+3], bl0,bl1);
                MMA4(d0,d1,d2,d3, al[4*kt],al[4*kt+1],al[4*kt+2],al[4*kt+3], bh0,bh1);
            }
            const int c0 = nt * 8 + (lane & 3) * 2;
            const float bb0 = s_b2[c0], bb1 = s_b2[c0 + 1];
            float2 v01 = make_float2(d0 + bb0, d1 + bb1);
            float2 v23 = make_float2(d2 + bb0, d3 + bb1);
            *(float2*)(out + (size_t)item0 * 64 + c0)       = v01;
            *(float2*)(out + (size_t)(item0 + 8) * 64 + c0) = v23;
        }
    }
}

// ---------------------------------------------------------------------------
extern "C" void kernel_launch(void* const* d_in, const int* in_sizes, int n_in,
                              void* d_out, int out_size)
{
    const int*   seqs = (const int*)  d_in[0];
    const int*   qtok = (const int*)  d_in[1];
    const float* emb  = (const float*)d_in[2];
    const float* sw1  = (const float*)d_in[3];
    const float* sb1  = (const float*)d_in[4];
    const float* sw2  = (const float*)d_in[5];
    const float* sb2  = (const float*)d_in[6];
    const float* w1   = (const float*)d_in[7];
    const float* b1   = (const float*)d_in[8];
    const float* w2   = (const float*)d_in[9];
    const float* b2   = (const float*)d_in[10];
    float* out = (float*)d_out;

    cudaFuncSetAttribute(main_k, cudaFuncAttributeMaxDynamicSharedMemorySize, SMEM_TOTAL);

    precompute_k<<<72, 128>>>(emb, sw1, sb1, sw2, sb2, w1, b1, w2);
    main_k<<<NB / 128, 256, SMEM_TOTAL>>>(seqs, qtok, b2, out);
}